// round 1
// baseline (speedup 1.0000x reference)
#include <cuda_runtime.h>
#include <math.h>

// ---------------------------------------------------------------------------
// AdaptiveDCA: x[8,512,64,64] -> qkv = w_qkv @ x  (per-batch GEMM 1536x512 @ 512x4096)
// then 4 dilated 3x3 attentions (dil = 1,2,4,8) over channel blocks of 128
// (2 heads x 64 dims each), gated by softmax(mean-pool(x) @ w_gate.T + b_gate).
// ---------------------------------------------------------------------------

#define BATCH    8
#define CIN      512
#define HW       4096      // 64*64
#define HH       64
#define WW       64
#define OCH      1536      // 3*512
#define NDIL     4
#define BD       128       // channels per dilation block
#define HPB      2         // heads per block
#define HD       64        // head dim
#define SCALE    0.125f    // HD^-0.5

// Scratch (static device globals — no runtime allocation)
__device__ float g_qkv[(size_t)BATCH * OCH * HW];   // 201 MB
__device__ float g_pooled[BATCH * CIN];
__device__ float g_gate[BATCH * NDIL];

// ---------------------------------------------------------------------------
// Pool: pooled[b,c] = mean over HW of x[b,c,:,:]
// ---------------------------------------------------------------------------
__global__ void pool_kernel(const float* __restrict__ x) {
    int c = blockIdx.x;
    int b = blockIdx.y;
    const float* p = x + ((size_t)b * CIN + c) * HW;
    float s = 0.f;
    for (int t = threadIdx.x; t < HW; t += blockDim.x) s += p[t];
    #pragma unroll
    for (int o = 16; o; o >>= 1) s += __shfl_xor_sync(0xffffffffu, s, o);
    __shared__ float red[8];
    int w = threadIdx.x >> 5;
    if ((threadIdx.x & 31) == 0) red[w] = s;
    __syncthreads();
    if (threadIdx.x < 8) {
        float v = red[threadIdx.x];
        #pragma unroll
        for (int o = 4; o; o >>= 1) v += __shfl_xor_sync(0xffu, v, o);
        if (threadIdx.x == 0) g_pooled[b * CIN + c] = v * (1.f / (float)HW);
    }
}

// ---------------------------------------------------------------------------
// Gate: gate[b,:] = softmax(pooled[b] @ w_gate.T + b_gate).  One warp per batch.
// ---------------------------------------------------------------------------
__global__ void gate_kernel(const float* __restrict__ w_gate,
                            const float* __restrict__ b_gate) {
    int b    = threadIdx.x >> 5;
    int lane = threadIdx.x & 31;
    float logit[NDIL];
    #pragma unroll
    for (int i = 0; i < NDIL; i++) {
        float s = 0.f;
        for (int c = lane; c < CIN; c += 32)
            s += g_pooled[b * CIN + c] * w_gate[i * CIN + c];
        #pragma unroll
        for (int o = 16; o; o >>= 1) s += __shfl_xor_sync(0xffffffffu, s, o);
        logit[i] = s + b_gate[i];
    }
    float m = fmaxf(fmaxf(logit[0], logit[1]), fmaxf(logit[2], logit[3]));
    float e[NDIL], sum = 0.f;
    #pragma unroll
    for (int i = 0; i < NDIL; i++) { e[i] = expf(logit[i] - m); sum += e[i]; }
    if (lane < NDIL) g_gate[b * NDIL + lane] = e[lane] / sum;
}

// ---------------------------------------------------------------------------
// GEMM: qkv[b] = w_qkv[1536x512] @ x[b][512x4096]
// 128x128 block tile, BK=16, 256 threads, 8x8 micro-tile (4+4 split layout)
// ---------------------------------------------------------------------------
#define BM 128
#define BN 128
#define BK 16
#define LDS 132   // padded leading dim

__global__ __launch_bounds__(256, 2)
void gemm_kernel(const float* __restrict__ x, const float* __restrict__ w) {
    __shared__ float As[BK][LDS];   // As[k][m]
    __shared__ float Bs[BK][LDS];   // Bs[k][n]

    const int bn = blockIdx.x * BN;
    const int bm = blockIdx.y * BM;
    const int b  = blockIdx.z;
    const float* B = x + (size_t)b * CIN * HW;
    float* C = g_qkv + (size_t)b * OCH * HW;

    const int tid = threadIdx.x;
    const int tm4 = (tid >> 4) << 2;   // 0..60
    const int tn4 = (tid & 15) << 2;   // 0..60

    float acc[8][8];
    #pragma unroll
    for (int i = 0; i < 8; i++)
        #pragma unroll
        for (int j = 0; j < 8; j++) acc[i][j] = 0.f;

    for (int k0 = 0; k0 < CIN; k0 += BK) {
        // Load A tile (128 rows x 16 k) as float4, store transposed
        #pragma unroll
        for (int t = 0; t < 2; t++) {
            int f   = tid + t * 256;          // 0..511 float4s
            int row = f >> 2;
            int kc  = (f & 3) << 2;
            float4 v = *(const float4*)(w + (size_t)(bm + row) * CIN + k0 + kc);
            As[kc + 0][row] = v.x;
            As[kc + 1][row] = v.y;
            As[kc + 2][row] = v.z;
            As[kc + 3][row] = v.w;
        }
        // Load B tile (16 k x 128 n) as float4
        #pragma unroll
        for (int t = 0; t < 2; t++) {
            int f  = tid + t * 256;
            int kr = f >> 5;
            int nc = (f & 31) << 2;
            *(float4*)&Bs[kr][nc] =
                *(const float4*)(B + (size_t)(k0 + kr) * HW + bn + nc);
        }
        __syncthreads();

        #pragma unroll
        for (int k = 0; k < BK; k++) {
            float4 a0 = *(const float4*)&As[k][tm4];
            float4 a1 = *(const float4*)&As[k][tm4 + 64];
            float4 b0 = *(const float4*)&Bs[k][tn4];
            float4 b1 = *(const float4*)&Bs[k][tn4 + 64];
            float ar[8] = {a0.x, a0.y, a0.z, a0.w, a1.x, a1.y, a1.z, a1.w};
            float br[8] = {b0.x, b0.y, b0.z, b0.w, b1.x, b1.y, b1.z, b1.w};
            #pragma unroll
            for (int i = 0; i < 8; i++)
                #pragma unroll
                for (int j = 0; j < 8; j++)
                    acc[i][j] = fmaf(ar[i], br[j], acc[i][j]);
        }
        __syncthreads();
    }

    // Write back (two float4 per row-slot)
    #pragma unroll
    for (int ii = 0; ii < 8; ii++) {
        int row = bm + tm4 + ((ii < 4) ? ii : (60 + ii));
        float4 v0 = make_float4(acc[ii][0], acc[ii][1], acc[ii][2], acc[ii][3]);
        float4 v1 = make_float4(acc[ii][4], acc[ii][5], acc[ii][6], acc[ii][7]);
        *(float4*)&C[(size_t)row * HW + bn + tn4]      = v0;
        *(float4*)&C[(size_t)row * HW + bn + tn4 + 64] = v1;
    }
}

// ---------------------------------------------------------------------------
// Dilated attention + gating. One warp per (b, dil, head, row, 32-col segment).
// Lane = spatial x -> every q/k/v access is a coalesced 128B line.
// Per-lane softmax over 9 taps (zero-padded taps score exactly 0, matching ref).
// ---------------------------------------------------------------------------
__global__ __launch_bounds__(256)
void attn_kernel(float* __restrict__ out) {
    int wt   = (blockIdx.x * blockDim.x + threadIdx.x) >> 5;
    int lane = threadIdx.x & 31;

    int seg = wt & 1;
    int y   = (wt >> 1) & 63;
    int h   = (wt >> 7) & 1;
    int i   = (wt >> 8) & 3;
    int b   = wt >> 10;

    int dil = 1 << i;               // 1,2,4,8
    int xx  = seg * 32 + lane;
    int n   = y * WW + xx;

    size_t base = (size_t)b * OCH * HW + (size_t)(i * BD + h * HD) * HW;
    const float* qp = g_qkv + base;
    const float* kp = g_qkv + base + (size_t)CIN * HW;        // +512 channels
    const float* vp = g_qkv + base + (size_t)(2 * CIN) * HW;  // +1024 channels

    int  nn[9];
    bool val[9];
    #pragma unroll
    for (int t = 0; t < 9; t++) {
        int dy = (t / 3 - 1) * dil;
        int dx = (t % 3 - 1) * dil;
        int yy = y + dy;
        int x2 = xx + dx;
        bool v = (yy >= 0) & (yy < HH) & (x2 >= 0) & (x2 < WW);
        val[t] = v;
        nn[t]  = v ? (yy * WW + x2) : 0;
    }

    float sc[9];
    #pragma unroll
    for (int t = 0; t < 9; t++) sc[t] = 0.f;

    #pragma unroll 2
    for (int c = 0; c < HD; c++) {
        float qv = qp[(size_t)c * HW + n];
        const float* kc = kp + (size_t)c * HW;
        #pragma unroll
        for (int t = 0; t < 9; t++)
            if (val[t]) sc[t] = fmaf(qv, kc[nn[t]], sc[t]);
    }

    // softmax over 9 taps (invalid taps hold score 0, included — matches zero-pad ref)
    float m = -1e30f;
    #pragma unroll
    for (int t = 0; t < 9; t++) { sc[t] *= SCALE; m = fmaxf(m, sc[t]); }
    float at[9], sum = 0.f;
    #pragma unroll
    for (int t = 0; t < 9; t++) { at[t] = expf(sc[t] - m); sum += at[t]; }
    float inv = 1.f / sum;
    #pragma unroll
    for (int t = 0; t < 9; t++) at[t] *= inv;

    float g = g_gate[b * NDIL + i];
    float* op = out + ((size_t)b * CIN + i * BD + h * HD) * HW;

    #pragma unroll 2
    for (int c = 0; c < HD; c++) {
        const float* vc = vp + (size_t)c * HW;
        float acc = 0.f;
        #pragma unroll
        for (int t = 0; t < 9; t++)
            if (val[t]) acc = fmaf(at[t], vc[nn[t]], acc);
        op[(size_t)c * HW + n] = acc * g;
    }
}

// ---------------------------------------------------------------------------
// Launch
// ---------------------------------------------------------------------------
extern "C" void kernel_launch(void* const* d_in, const int* in_sizes, int n_in,
                              void* d_out, int out_size) {
    const float* x      = (const float*)d_in[0];
    const float* w_qkv  = (const float*)d_in[1];
    const float* w_gate = (const float*)d_in[2];
    const float* b_gate = (const float*)d_in[3];
    float* out = (float*)d_out;

    pool_kernel<<<dim3(CIN, BATCH), 256>>>(x);
    gate_kernel<<<1, BATCH * 32>>>(w_gate, b_gate);
    gemm_kernel<<<dim3(HW / BN, OCH / BM, BATCH), 256>>>(x, w_qkv);
    // warps: 8 b * 4 dil * 2 heads * 64 rows * 2 segs = 8192 -> 1024 blocks x 8 warps
    attn_kernel<<<1024, 256>>>(out);
}

// round 3
// speedup vs baseline: 1.6005x; 1.6005x over previous
#include <cuda_runtime.h>
#include <cuda_bf16.h>
#include <math.h>
#include <stdint.h>

// ---------------------------------------------------------------------------
// AdaptiveDCA: qkv = w_qkv @ x per batch (1536x512 @ 512x4096) via mma.sync
// bf16 3-pass hi/lo split (baseline PTX, no 'a'-target features), then 4
// dilated 3x3 attentions, gated concat.
// ---------------------------------------------------------------------------

#define BATCH    8
#define CIN      512
#define HW       4096
#define HH       64
#define WW       64
#define OCH      1536
#define NDIL     4
#define BD       128
#define HD       64
#define SCALE    0.125f

// Scratch (static device globals)
__device__ float g_qkv[(size_t)BATCH * OCH * HW];               // 201 MB
__device__ float g_pooled[BATCH * CIN];
__device__ float g_gate[BATCH * NDIL];
__device__ __nv_bfloat16 g_whi[OCH * CIN];
__device__ __nv_bfloat16 g_wlo[OCH * CIN];
__device__ __nv_bfloat16 g_xhi[(size_t)BATCH * CIN * HW];       // [b][c][n]
__device__ __nv_bfloat16 g_xlo[(size_t)BATCH * CIN * HW];

// ============================ PTX helpers ==================================
__device__ __forceinline__ uint32_t smem_u32(const void* p) {
    uint32_t a;
    asm("{ .reg .u64 t; cvta.to.shared.u64 t, %1; cvt.u32.u64 %0, t; }" : "=r"(a) : "l"(p));
    return a;
}
#define CP16(dst, src) \
    asm volatile("cp.async.cg.shared.global [%0], [%1], 16;" :: "r"(dst), "l"(src))
#define CP_COMMIT() asm volatile("cp.async.commit_group;" ::: "memory")
#define CP_WAIT(n)  asm volatile("cp.async.wait_group %0;" :: "n"(n) : "memory")

#define LDSM_X4(r, a)                                                         \
    asm volatile("ldmatrix.sync.aligned.m8n8.x4.shared.b16 {%0,%1,%2,%3}, [%4];" \
        : "=r"((r)[0]), "=r"((r)[1]), "=r"((r)[2]), "=r"((r)[3]) : "r"(a))
#define LDSM_X4T(r0, r1, r2, r3, a)                                           \
    asm volatile("ldmatrix.sync.aligned.m8n8.x4.trans.shared.b16 {%0,%1,%2,%3}, [%4];" \
        : "=r"(r0), "=r"(r1), "=r"(r2), "=r"(r3) : "r"(a))

#define MMA16816(d, a, b)                                                     \
    asm volatile("mma.sync.aligned.m16n8k16.row.col.f32.bf16.bf16.f32 "       \
        "{%0,%1,%2,%3}, {%4,%5,%6,%7}, {%8,%9}, {%0,%1,%2,%3};"               \
        : "+f"((d)[0]), "+f"((d)[1]), "+f"((d)[2]), "+f"((d)[3])              \
        : "r"((a)[0]), "r"((a)[1]), "r"((a)[2]), "r"((a)[3]),                 \
          "r"((b)[0]), "r"((b)[1]))

// ============================ Conversion ===================================
__global__ void conv_w_kernel(const float* __restrict__ w) {
    int i = (blockIdx.x * 256 + threadIdx.x) * 4;
    float4 v = *(const float4*)(w + i);
    float vv[4] = {v.x, v.y, v.z, v.w};
    #pragma unroll
    for (int j = 0; j < 4; j++) {
        __nv_bfloat16 hi = __float2bfloat16(vv[j]);
        __nv_bfloat16 lo = __float2bfloat16(vv[j] - __bfloat162float(hi));
        g_whi[i + j] = hi;
        g_wlo[i + j] = lo;
    }
}

__global__ void conv_x_kernel(const float* __restrict__ x) {
    size_t i = ((size_t)blockIdx.x * 256 + threadIdx.x) * 4;
    float4 v = *(const float4*)(x + i);
    float vv[4] = {v.x, v.y, v.z, v.w};
    #pragma unroll
    for (int j = 0; j < 4; j++) {
        __nv_bfloat16 hi = __float2bfloat16(vv[j]);
        __nv_bfloat16 lo = __float2bfloat16(vv[j] - __bfloat162float(hi));
        g_xhi[i + j] = hi;
        g_xlo[i + j] = lo;
    }
}

// ============================ MMA GEMM =====================================
// CTA 128x128, BK=32, 8 warps of 64m x 32n, double-buffered cp.async.
// SMEM per stage: Whi/Wlo 128x32 @ stride 40 bf16 (80B), Xhi/Xlo 32x128
// @ stride 136 bf16 (272B). Conflict-free for ldmatrix / ldmatrix.trans.
#define W_STRIDE_B 80
#define X_STRIDE_B 272
#define W_HALF_B   10240       // 128 * 80
#define X_HALF_B   8704        // 32 * 272
#define STAGE_B    37888       // 2*W_HALF_B + 2*X_HALF_B
#define GEMM_SMEM  (2 * STAGE_B)

__global__ __launch_bounds__(256)
void gemm_mma_kernel() {
    extern __shared__ __align__(1024) char smem[];
    const uint32_t sb = smem_u32(smem);

    const int tid  = threadIdx.x;
    const int lane = tid & 31;
    const int w    = tid >> 5;
    const int wm   = w & 1;        // 0..1  (64-row halves)
    const int wn   = w >> 1;       // 0..3  (32-col quarters)

    const int n0 = blockIdx.x * 128;
    const int m0 = blockIdx.y * 128;
    const int b  = blockIdx.z;

    const __nv_bfloat16* Wh = g_whi + (size_t)m0 * CIN;
    const __nv_bfloat16* Wl = g_wlo + (size_t)m0 * CIN;
    const __nv_bfloat16* Xh = g_xhi + (size_t)b * CIN * HW + n0;
    const __nv_bfloat16* Xl = g_xlo + (size_t)b * CIN * HW + n0;

    float acc[4][4][4];
    #pragma unroll
    for (int mt = 0; mt < 4; mt++)
        #pragma unroll
        for (int nt = 0; nt < 4; nt++)
            #pragma unroll
            for (int q = 0; q < 4; q++) acc[mt][nt][q] = 0.f;

    // ldmatrix per-lane address components
    const uint32_t lrow  = (lane & 7) + (lane & 8);   // 0..15
    const uint32_t lcol8 = (lane >> 4) << 3;          // 0 or 8

    // -------- global -> smem stage loader --------
    // W chunks: idx 0..511 per half: r = idx>>2 (row), c = idx&3 (16B col)
    const int wr = tid >> 2, wc = tid & 3;
    // X chunks: idx 0..511 per half: kr = idx>>4, c = idx&15
    const int xr = tid >> 4, xc = tid & 15;

    #define LOAD_STAGE(s, it)                                                 \
    do {                                                                      \
        const int k0 = (it) * 32;                                             \
        const uint32_t wbase = sb + (s) * STAGE_B;                            \
        const uint32_t xbase = wbase + 2 * W_HALF_B;                          \
        _Pragma("unroll")                                                     \
        for (int t = 0; t < 2; t++) {                                         \
            int r = wr + t * 64, c = wc;                                      \
            uint32_t d = wbase + r * W_STRIDE_B + c * 16;                     \
            size_t so = (size_t)r * CIN + k0 + c * 8;                         \
            CP16(d, Wh + so);                                                 \
            CP16(d + W_HALF_B, Wl + so);                                      \
        }                                                                     \
        _Pragma("unroll")                                                     \
        for (int t = 0; t < 2; t++) {                                         \
            int kr = xr + t * 16, c = xc;                                     \
            uint32_t d = xbase + kr * X_STRIDE_B + c * 16;                    \
            size_t so = (size_t)(k0 + kr) * HW + c * 8;                       \
            CP16(d, Xh + so);                                                 \
            CP16(d + X_HALF_B, Xl + so);                                      \
        }                                                                     \
        CP_COMMIT();                                                          \
    } while (0)

    LOAD_STAGE(0, 0);

    for (int it = 0; it < 16; it++) {
        const int s = it & 1;
        if (it + 1 < 16) {
            LOAD_STAGE(s ^ 1, it + 1);
            CP_WAIT(1);
        } else {
            CP_WAIT(0);
        }
        __syncthreads();

        const uint32_t sWh = sb + s * STAGE_B;
        const uint32_t sWl = sWh + W_HALF_B;
        const uint32_t sXh = sWh + 2 * W_HALF_B;
        const uint32_t sXl = sXh + X_HALF_B;

        #pragma unroll
        for (int ks = 0; ks < 2; ks++) {
            uint32_t Ah[4][4], Al[4][4], Bh[4][2], Bl[4][2];
            #pragma unroll
            for (int mt = 0; mt < 4; mt++) {
                uint32_t off = (wm * 64 + mt * 16 + lrow) * W_STRIDE_B
                             + (ks * 16 + lcol8) * 2;
                LDSM_X4(Ah[mt], sWh + off);
                LDSM_X4(Al[mt], sWl + off);
            }
            #pragma unroll
            for (int n2 = 0; n2 < 2; n2++) {
                uint32_t off = (ks * 16 + lrow) * X_STRIDE_B
                             + (wn * 32 + n2 * 16 + lcol8) * 2;
                LDSM_X4T(Bh[2 * n2][0], Bh[2 * n2][1],
                         Bh[2 * n2 + 1][0], Bh[2 * n2 + 1][1], sXh + off);
                LDSM_X4T(Bl[2 * n2][0], Bl[2 * n2][1],
                         Bl[2 * n2 + 1][0], Bl[2 * n2 + 1][1], sXl + off);
            }
            #pragma unroll
            for (int mt = 0; mt < 4; mt++)
                #pragma unroll
                for (int nt = 0; nt < 4; nt++) {
                    MMA16816(acc[mt][nt], Ah[mt], Bh[nt]);
                    MMA16816(acc[mt][nt], Al[mt], Bh[nt]);
                    MMA16816(acc[mt][nt], Ah[mt], Bl[nt]);
                }
        }
        __syncthreads();
    }

    // -------- epilogue --------
    const int gid = lane >> 2, tig = lane & 3;
    float* C = g_qkv + ((size_t)b * OCH + m0 + wm * 64) * HW + n0 + wn * 32;
    #pragma unroll
    for (int mt = 0; mt < 4; mt++)
        #pragma unroll
        for (int nt = 0; nt < 4; nt++) {
            float2 v0 = make_float2(acc[mt][nt][0], acc[mt][nt][1]);
            float2 v1 = make_float2(acc[mt][nt][2], acc[mt][nt][3]);
            size_t r0 = (size_t)(mt * 16 + gid) * HW + nt * 8 + tig * 2;
            *(float2*)(C + r0)            = v0;
            *(float2*)(C + r0 + 8 * HW)   = v1;
        }
}

// ============================ Pool / Gate ==================================
__global__ void pool_kernel(const float* __restrict__ x) {
    int c = blockIdx.x, b = blockIdx.y;
    const float* p = x + ((size_t)b * CIN + c) * HW;
    float s = 0.f;
    for (int t = threadIdx.x; t < HW; t += blockDim.x) s += p[t];
    #pragma unroll
    for (int o = 16; o; o >>= 1) s += __shfl_xor_sync(0xffffffffu, s, o);
    __shared__ float red[8];
    if ((threadIdx.x & 31) == 0) red[threadIdx.x >> 5] = s;
    __syncthreads();
    if (threadIdx.x < 8) {
        float v = red[threadIdx.x];
        #pragma unroll
        for (int o = 4; o; o >>= 1) v += __shfl_xor_sync(0xffu, v, o);
        if (threadIdx.x == 0) g_pooled[b * CIN + c] = v * (1.f / (float)HW);
    }
}

__global__ void gate_kernel(const float* __restrict__ w_gate,
                            const float* __restrict__ b_gate) {
    int b = threadIdx.x >> 5, lane = threadIdx.x & 31;
    float logit[NDIL];
    #pragma unroll
    for (int i = 0; i < NDIL; i++) {
        float s = 0.f;
        for (int c = lane; c < CIN; c += 32)
            s += g_pooled[b * CIN + c] * w_gate[i * CIN + c];
        #pragma unroll
        for (int o = 16; o; o >>= 1) s += __shfl_xor_sync(0xffffffffu, s, o);
        logit[i] = s + b_gate[i];
    }
    float m = fmaxf(fmaxf(logit[0], logit[1]), fmaxf(logit[2], logit[3]));
    float e[NDIL], sum = 0.f;
    #pragma unroll
    for (int i = 0; i < NDIL; i++) { e[i] = expf(logit[i] - m); sum += e[i]; }
    if (lane < NDIL) g_gate[b * NDIL + lane] = e[lane] / sum;
}

// ============================ Attention ====================================
__global__ __launch_bounds__(256)
void attn_kernel(float* __restrict__ out) {
    int wt   = (blockIdx.x * blockDim.x + threadIdx.x) >> 5;
    int lane = threadIdx.x & 31;

    int seg = wt & 1;
    int y   = (wt >> 1) & 63;
    int h   = (wt >> 7) & 1;
    int i   = (wt >> 8) & 3;
    int b   = wt >> 10;

    int dil = 1 << i;
    int xx  = seg * 32 + lane;
    int n   = y * WW + xx;

    size_t base = (size_t)b * OCH * HW + (size_t)(i * BD + h * HD) * HW;
    const float* qp = g_qkv + base;
    const float* kp = g_qkv + base + (size_t)CIN * HW;
    const float* vp = g_qkv + base + (size_t)(2 * CIN) * HW;

    int  nn[9];
    bool val[9];
    #pragma unroll
    for (int t = 0; t < 9; t++) {
        int dy = (t / 3 - 1) * dil;
        int dx = (t % 3 - 1) * dil;
        int yy = y + dy, x2 = xx + dx;
        bool v = (yy >= 0) & (yy < HH) & (x2 >= 0) & (x2 < WW);
        val[t] = v;
        nn[t]  = v ? (yy * WW + x2) : 0;
    }

    float sc[9];
    #pragma unroll
    for (int t = 0; t < 9; t++) sc[t] = 0.f;

    #pragma unroll 2
    for (int c = 0; c < HD; c++) {
        float qv = qp[(size_t)c * HW + n];
        const float* kc = kp + (size_t)c * HW;
        #pragma unroll
        for (int t = 0; t < 9; t++)
            if (val[t]) sc[t] = fmaf(qv, kc[nn[t]], sc[t]);
    }

    float m = -1e30f;
    #pragma unroll
    for (int t = 0; t < 9; t++) { sc[t] *= SCALE; m = fmaxf(m, sc[t]); }
    float at[9], sum = 0.f;
    #pragma unroll
    for (int t = 0; t < 9; t++) { at[t] = expf(sc[t] - m); sum += at[t]; }
    float inv = 1.f / sum;
    #pragma unroll
    for (int t = 0; t < 9; t++) at[t] *= inv;

    float g = g_gate[b * NDIL + i];
    float* op = out + ((size_t)b * CIN + i * BD + h * HD) * HW;

    #pragma unroll 2
    for (int c = 0; c < HD; c++) {
        const float* vc = vp + (size_t)c * HW;
        float acc = 0.f;
        #pragma unroll
        for (int t = 0; t < 9; t++)
            if (val[t]) acc = fmaf(at[t], vc[nn[t]], acc);
        op[(size_t)c * HW + n] = acc * g;
    }
}

// ============================ Launch =======================================
extern "C" void kernel_launch(void* const* d_in, const int* in_sizes, int n_in,
                              void* d_out, int out_size) {
    const float* x      = (const float*)d_in[0];
    const float* w_qkv  = (const float*)d_in[1];
    const float* w_gate = (const float*)d_in[2];
    const float* b_gate = (const float*)d_in[3];
    float* out = (float*)d_out;

    cudaFuncSetAttribute(gemm_mma_kernel,
                         cudaFuncAttributeMaxDynamicSharedMemorySize, GEMM_SMEM);

    conv_w_kernel<<<OCH * CIN / 1024, 256>>>(w_qkv);
    conv_x_kernel<<<(int)((size_t)BATCH * CIN * HW / 1024), 256>>>(x);
    pool_kernel<<<dim3(CIN, BATCH), 256>>>(x);
    gate_kernel<<<1, BATCH * 32>>>(w_gate, b_gate);
    gemm_mma_kernel<<<dim3(HW / 128, OCH / 128, BATCH), 256, GEMM_SMEM>>>();
    attn_kernel<<<1024, 256>>>(out);
}

// round 4
// speedup vs baseline: 1.6120x; 1.0072x over previous
#include <cuda_runtime.h>
#include <cuda_bf16.h>
#include <math.h>
#include <stdint.h>

// ---------------------------------------------------------------------------
// AdaptiveDCA: qkv = w_qkv @ x per batch (1536x512 @ 512x4096) via mma.sync
// bf16 3-pass hi/lo split, 3-stage cp.async pipeline; then 4 dilated 3x3
// attentions, gated concat.
// ---------------------------------------------------------------------------

#define BATCH    8
#define CIN      512
#define HW       4096
#define HH       64
#define WW       64
#define OCH      1536
#define NDIL     4
#define BD       128
#define HD       64
#define SCALE    0.125f

__device__ float g_qkv[(size_t)BATCH * OCH * HW];               // 201 MB
__device__ float g_pooled[BATCH * CIN];
__device__ float g_gate[BATCH * NDIL];
__device__ __nv_bfloat16 g_whi[OCH * CIN];
__device__ __nv_bfloat16 g_wlo[OCH * CIN];
__device__ __nv_bfloat16 g_xhi[(size_t)BATCH * CIN * HW];       // [b][c][n]
__device__ __nv_bfloat16 g_xlo[(size_t)BATCH * CIN * HW];

// ============================ PTX helpers ==================================
__device__ __forceinline__ uint32_t smem_u32(const void* p) {
    uint32_t a;
    asm("{ .reg .u64 t; cvta.to.shared.u64 t, %1; cvt.u32.u64 %0, t; }" : "=r"(a) : "l"(p));
    return a;
}
#define CP16(dst, src) \
    asm volatile("cp.async.cg.shared.global [%0], [%1], 16;" :: "r"(dst), "l"(src))
#define CP_COMMIT() asm volatile("cp.async.commit_group;" ::: "memory")
#define CP_WAIT(n)  asm volatile("cp.async.wait_group %0;" :: "n"(n) : "memory")

#define LDSM_X4(r, a)                                                         \
    asm volatile("ldmatrix.sync.aligned.m8n8.x4.shared.b16 {%0,%1,%2,%3}, [%4];" \
        : "=r"((r)[0]), "=r"((r)[1]), "=r"((r)[2]), "=r"((r)[3]) : "r"(a))
#define LDSM_X4T(r0, r1, r2, r3, a)                                           \
    asm volatile("ldmatrix.sync.aligned.m8n8.x4.trans.shared.b16 {%0,%1,%2,%3}, [%4];" \
        : "=r"(r0), "=r"(r1), "=r"(r2), "=r"(r3) : "r"(a))

#define MMA16816(d, a, b)                                                     \
    asm volatile("mma.sync.aligned.m16n8k16.row.col.f32.bf16.bf16.f32 "       \
        "{%0,%1,%2,%3}, {%4,%5,%6,%7}, {%8,%9}, {%0,%1,%2,%3};"               \
        : "+f"((d)[0]), "+f"((d)[1]), "+f"((d)[2]), "+f"((d)[3])              \
        : "r"((a)[0]), "r"((a)[1]), "r"((a)[2]), "r"((a)[3]),                 \
          "r"((b)[0]), "r"((b)[1]))

// ============================ Conversion ===================================
__global__ void conv_w_kernel(const float* __restrict__ w) {
    int i = (blockIdx.x * 256 + threadIdx.x) * 4;
    float4 v = *(const float4*)(w + i);
    float vv[4] = {v.x, v.y, v.z, v.w};
    #pragma unroll
    for (int j = 0; j < 4; j++) {
        __nv_bfloat16 hi = __float2bfloat16(vv[j]);
        __nv_bfloat16 lo = __float2bfloat16(vv[j] - __bfloat162float(hi));
        g_whi[i + j] = hi;
        g_wlo[i + j] = lo;
    }
}

__global__ void conv_x_kernel(const float* __restrict__ x) {
    size_t i = ((size_t)blockIdx.x * 256 + threadIdx.x) * 4;
    float4 v = *(const float4*)(x + i);
    float vv[4] = {v.x, v.y, v.z, v.w};
    #pragma unroll
    for (int j = 0; j < 4; j++) {
        __nv_bfloat16 hi = __float2bfloat16(vv[j]);
        __nv_bfloat16 lo = __float2bfloat16(vv[j] - __bfloat162float(hi));
        g_xhi[i + j] = hi;
        g_xlo[i + j] = lo;
    }
}

// ============================ MMA GEMM =====================================
// CTA 128x128, BK=32, 8 warps of 64m x 32n. 3-stage cp.async pipeline,
// ONE __syncthreads per k-iteration (wait -> sync -> issue 2-ahead -> compute).
#define W_STRIDE_B 80
#define X_STRIDE_B 272
#define W_HALF_B   10240       // 128 * 80
#define X_HALF_B   8704        // 32 * 272
#define STAGE_B    37888       // 2*W_HALF_B + 2*X_HALF_B
#define NSTAGE     3
#define GEMM_SMEM  (NSTAGE * STAGE_B)

__global__ __launch_bounds__(256)
void gemm_mma_kernel() {
    extern __shared__ __align__(1024) char smem[];
    const uint32_t sb = smem_u32(smem);

    const int tid  = threadIdx.x;
    const int lane = tid & 31;
    const int w    = tid >> 5;
    const int wm   = w & 1;
    const int wn   = w >> 1;

    const int n0 = blockIdx.x * 128;
    const int m0 = blockIdx.y * 128;
    const int b  = blockIdx.z;

    const __nv_bfloat16* Wh = g_whi + (size_t)m0 * CIN;
    const __nv_bfloat16* Wl = g_wlo + (size_t)m0 * CIN;
    const __nv_bfloat16* Xh = g_xhi + (size_t)b * CIN * HW + n0;
    const __nv_bfloat16* Xl = g_xlo + (size_t)b * CIN * HW + n0;

    float acc[4][4][4];
    #pragma unroll
    for (int mt = 0; mt < 4; mt++)
        #pragma unroll
        for (int nt = 0; nt < 4; nt++)
            #pragma unroll
            for (int q = 0; q < 4; q++) acc[mt][nt][q] = 0.f;

    const uint32_t lrow  = (lane & 7) + (lane & 8);
    const uint32_t lcol8 = (lane >> 4) << 3;

    const int wr = tid >> 2, wc = tid & 3;
    const int xr = tid >> 4, xc = tid & 15;

    #define LOAD_STAGE(s, it)                                                 \
    do {                                                                      \
        const int k0 = (it) * 32;                                             \
        const uint32_t wbase = sb + (s) * STAGE_B;                            \
        const uint32_t xbase = wbase + 2 * W_HALF_B;                          \
        _Pragma("unroll")                                                     \
        for (int t = 0; t < 2; t++) {                                         \
            int r = wr + t * 64, c = wc;                                      \
            uint32_t d = wbase + r * W_STRIDE_B + c * 16;                     \
            size_t so = (size_t)r * CIN + k0 + c * 8;                         \
            CP16(d, Wh + so);                                                 \
            CP16(d + W_HALF_B, Wl + so);                                      \
        }                                                                     \
        _Pragma("unroll")                                                     \
        for (int t = 0; t < 2; t++) {                                         \
            int kr = xr + t * 16, c = xc;                                     \
            uint32_t d = xbase + kr * X_STRIDE_B + c * 16;                    \
            size_t so = (size_t)(k0 + kr) * HW + c * 8;                       \
            CP16(d, Xh + so);                                                 \
            CP16(d + X_HALF_B, Xl + so);                                      \
        }                                                                     \
        CP_COMMIT();                                                          \
    } while (0)

    LOAD_STAGE(0, 0);
    LOAD_STAGE(1, 1);

    for (int it = 0; it < 16; it++) {
        if (it < 15) CP_WAIT(1);
        else         CP_WAIT(0);
        __syncthreads();

        if (it + 2 < 16) {
            int s2 = (it + 2) % NSTAGE;
            LOAD_STAGE(s2, it + 2);
        }

        const int s = it % NSTAGE;
        const uint32_t sWh = sb + s * STAGE_B;
        const uint32_t sWl = sWh + W_HALF_B;
        const uint32_t sXh = sWh + 2 * W_HALF_B;
        const uint32_t sXl = sXh + X_HALF_B;

        #pragma unroll
        for (int ks = 0; ks < 2; ks++) {
            uint32_t Ah[4][4], Al[4][4], Bh[4][2], Bl[4][2];
            #pragma unroll
            for (int mt = 0; mt < 4; mt++) {
                uint32_t off = (wm * 64 + mt * 16 + lrow) * W_STRIDE_B
                             + (ks * 16 + lcol8) * 2;
                LDSM_X4(Ah[mt], sWh + off);
                LDSM_X4(Al[mt], sWl + off);
            }
            #pragma unroll
            for (int n2 = 0; n2 < 2; n2++) {
                uint32_t off = (ks * 16 + lrow) * X_STRIDE_B
                             + (wn * 32 + n2 * 16 + lcol8) * 2;
                LDSM_X4T(Bh[2 * n2][0], Bh[2 * n2][1],
                         Bh[2 * n2 + 1][0], Bh[2 * n2 + 1][1], sXh + off);
                LDSM_X4T(Bl[2 * n2][0], Bl[2 * n2][1],
                         Bl[2 * n2 + 1][0], Bl[2 * n2 + 1][1], sXl + off);
            }
            #pragma unroll
            for (int mt = 0; mt < 4; mt++)
                #pragma unroll
                for (int nt = 0; nt < 4; nt++) {
                    MMA16816(acc[mt][nt], Ah[mt], Bh[nt]);
                    MMA16816(acc[mt][nt], Al[mt], Bh[nt]);
                    MMA16816(acc[mt][nt], Ah[mt], Bl[nt]);
                }
        }
    }

    const int gid = lane >> 2, tig = lane & 3;
    float* C = g_qkv + ((size_t)b * OCH + m0 + wm * 64) * HW + n0 + wn * 32;
    #pragma unroll
    for (int mt = 0; mt < 4; mt++)
        #pragma unroll
        for (int nt = 0; nt < 4; nt++) {
            float2 v0 = make_float2(acc[mt][nt][0], acc[mt][nt][1]);
            float2 v1 = make_float2(acc[mt][nt][2], acc[mt][nt][3]);
            size_t r0 = (size_t)(mt * 16 + gid) * HW + nt * 8 + tig * 2;
            *(float2*)(C + r0)          = v0;
            *(float2*)(C + r0 + 8 * HW) = v1;
        }
}

// ============================ Pool / Gate ==================================
__global__ void pool_kernel(const float* __restrict__ x) {
    int c = blockIdx.x, b = blockIdx.y;
    const float* p = x + ((size_t)b * CIN + c) * HW;
    float s = 0.f;
    for (int t = threadIdx.x; t < HW; t += blockDim.x) s += p[t];
    #pragma unroll
    for (int o = 16; o; o >>= 1) s += __shfl_xor_sync(0xffffffffu, s, o);
    __shared__ float red[8];
    if ((threadIdx.x & 31) == 0) red[threadIdx.x >> 5] = s;
    __syncthreads();
    if (threadIdx.x < 8) {
        float v = red[threadIdx.x];
        #pragma unroll
        for (int o = 4; o; o >>= 1) v += __shfl_xor_sync(0xffu, v, o);
        if (threadIdx.x == 0) g_pooled[b * CIN + c] = v * (1.f / (float)HW);
    }
}

__global__ void gate_kernel(const float* __restrict__ w_gate,
                            const float* __restrict__ b_gate) {
    int b = threadIdx.x >> 5, lane = threadIdx.x & 31;
    float logit[NDIL];
    #pragma unroll
    for (int i = 0; i < NDIL; i++) {
        float s = 0.f;
        for (int c = lane; c < CIN; c += 32)
            s += g_pooled[b * CIN + c] * w_gate[i * CIN + c];
        #pragma unroll
        for (int o = 16; o; o >>= 1) s += __shfl_xor_sync(0xffffffffu, s, o);
        logit[i] = s + b_gate[i];
    }
    float m = fmaxf(fmaxf(logit[0], logit[1]), fmaxf(logit[2], logit[3]));
    float e[NDIL], sum = 0.f;
    #pragma unroll
    for (int i = 0; i < NDIL; i++) { e[i] = expf(logit[i] - m); sum += e[i]; }
    if (lane < NDIL) g_gate[b * NDIL + lane] = e[lane] / sum;
}

// ============================ Attention ====================================
__global__ __launch_bounds__(256, 3)
void attn_kernel(float* __restrict__ out) {
    int wt   = (blockIdx.x * blockDim.x + threadIdx.x) >> 5;
    int lane = threadIdx.x & 31;

    int seg = wt & 1;
    int y   = (wt >> 1) & 63;
    int h   = (wt >> 7) & 1;
    int i   = (wt >> 8) & 3;
    int b   = wt >> 10;

    int dil = 1 << i;
    int xx  = seg * 32 + lane;
    int n   = y * WW + xx;

    size_t base = (size_t)b * OCH * HW + (size_t)(i * BD + h * HD) * HW;
    const float* qp = g_qkv + base;
    const float* kp = g_qkv + base + (size_t)CIN * HW;
    const float* vp = g_qkv + base + (size_t)(2 * CIN) * HW;

    int  nn[9];
    bool val[9];
    #pragma unroll
    for (int t = 0; t < 9; t++) {
        int dy = (t / 3 - 1) * dil;
        int dx = (t % 3 - 1) * dil;
        int yy = y + dy, x2 = xx + dx;
        bool v = (yy >= 0) & (yy < HH) & (x2 >= 0) & (x2 < WW);
        val[t] = v;
        nn[t]  = v ? (yy * WW + x2) : 0;
    }

    float sc[9];
    #pragma unroll
    for (int t = 0; t < 9; t++) sc[t] = 0.f;

    #pragma unroll 4
    for (int c = 0; c < HD; c++) {
        float qv = qp[(size_t)c * HW + n];
        const float* kc = kp + (size_t)c * HW;
        #pragma unroll
        for (int t = 0; t < 9; t++)
            if (val[t]) sc[t] = fmaf(qv, kc[nn[t]], sc[t]);
    }

    float m = -1e30f;
    #pragma unroll
    for (int t = 0; t < 9; t++) { sc[t] *= SCALE; m = fmaxf(m, sc[t]); }
    float at[9], sum = 0.f;
    #pragma unroll
    for (int t = 0; t < 9; t++) { at[t] = expf(sc[t] - m); sum += at[t]; }
    float inv = 1.f / sum;
    #pragma unroll
    for (int t = 0; t < 9; t++) at[t] *= inv;

    float g = g_gate[b * NDIL + i];
    float* op = out + ((size_t)b * CIN + i * BD + h * HD) * HW;

    #pragma unroll 4
    for (int c = 0; c < HD; c++) {
        const float* vc = vp + (size_t)c * HW;
        float acc = 0.f;
        #pragma unroll
        for (int t = 0; t < 9; t++)
            if (val[t]) acc = fmaf(at[t], vc[nn[t]], acc);
        op[(size_t)c * HW + n] = acc * g;
    }
}

// ============================ Launch =======================================
extern "C" void kernel_launch(void* const* d_in, const int* in_sizes, int n_in,
                              void* d_out, int out_size) {
    const float* x      = (const float*)d_in[0];
    const float* w_qkv  = (const float*)d_in[1];
    const float* w_gate = (const float*)d_in[2];
    const float* b_gate = (const float*)d_in[3];
    float* out = (float*)d_out;

    cudaFuncSetAttribute(gemm_mma_kernel,
                         cudaFuncAttributeMaxDynamicSharedMemorySize, GEMM_SMEM);

    conv_w_kernel<<<OCH * CIN / 1024, 256>>>(w_qkv);
    conv_x_kernel<<<(int)((size_t)BATCH * CIN * HW / 1024), 256>>>(x);
    pool_kernel<<<dim3(CIN, BATCH), 256>>>(x);
    gate_kernel<<<1, BATCH * 32>>>(w_gate, b_gate);
    gemm_mma_kernel<<<dim3(HW / 128, OCH / 128, BATCH), 256, GEMM_SMEM>>>();
    attn_kernel<<<1024, 256>>>(out);
}